// round 10
// baseline (speedup 1.0000x reference)
#include <cuda_runtime.h>

#define NN 100000
#define NE 1600000
#define NG 16
#define PERG (NE / NG)      // 100000 edges per graph segment
#define TSTEP (NN / NG)     // 6250 threshold step
#define BN_EPS 1e-5f
#define MAXDEG 64
#define FULLMASK 0xffffffffu

typedef unsigned long long u64;

// ---------------- scratch ----------------------------------------------------
__device__ float g_h1[NN * 64];     // MLP1 output (post-relu, pre-BN)
__device__ float g_y[NN * 32];      // y = W1a^T x per node
__device__ int   g_adj[NN * MAXDEG];
__device__ int   g_ideg[NN];
__device__ float g_stats1[128];
__device__ float g_stats2[128];
__device__ float g_gsum[NG * 64];
__device__ float g_cnt[NG];
__device__ int   g_ctr[4];          // work-steal counters: 0=prep-y 1=mlp1 2=mlp2

// ---------------- helpers ----------------------------------------------------
__device__ __forceinline__ u64 pk2(float lo, float hi) {
    u64 r; asm("mov.b64 %0, {%1,%2};" : "=l"(r) : "f"(lo), "f"(hi)); return r;
}
__device__ __forceinline__ void upk2(u64 v, float& a, float& b) {
    asm("mov.b64 {%0,%1}, %2;" : "=f"(a), "=f"(b) : "l"(v));
}
__device__ __forceinline__ u64 ffma2(u64 a, u64 b, u64 c) {
    u64 d; asm("fma.rn.f32x2 %0, %1, %2, %3;" : "=l"(d) : "l"(a), "l"(b), "l"(c));
    return d;
}
__device__ __forceinline__ u64 add2(u64 a, u64 b) {
    u64 d; asm("add.rn.f32x2 %0, %1, %2;" : "=l"(d) : "l"(a), "l"(b));
    return d;
}
__device__ __forceinline__ u64 relu2(u64 v) {
    float a, b; upk2(v, a, b);
    return pk2(fmaxf(a, 0.f), fmaxf(b, 0.f));
}
__device__ __forceinline__ int steal_tile(int* ctr, int lane) {
    int t;
    if (lane == 0) t = atomicAdd(ctr, 1);
    return __shfl_sync(FULLMASK, t, 0);
}

// Table: per warp, 64 rows x 10 u64 (16 nodes = 8 pairs, stride 20 floats).
#define ROW_U64 10
#define TBL_U64 (64 * ROW_U64)          // 640 u64 per warp
#define TILE_N 16
#define NTILES (NN / TILE_N)            // 6250 exact

#define PREP_YB 196                      // y blocks in prep kernel
#define PREP_AB 1563                     // edge blocks (1024 edges each)

// ---------------- small kernels ----------------------------------------------
__global__ void zero_kernel() {
    int i = blockIdx.x * blockDim.x + threadIdx.x;
    if (i < NN) g_ideg[i] = 0;
    if (i < 128) { g_stats1[i] = 0.f; g_stats2[i] = 0.f; }
    if (i < NG * 64) g_gsum[i] = 0.f;
    if (i < NG) g_cnt[i] = 0.f;
    if (i < 4) g_ctr[i] = 0;
}

// ---------------- prep: y = W1a^T x (blocks < PREP_YB) + adjacency build -----
__global__ __launch_bounds__(256, 4) void prep_kernel(
    const float* __restrict__ x, const int* __restrict__ ei,
    const float* __restrict__ W1a) {
    if (blockIdx.x >= PREP_YB) {
        // ---- edge path: build adjacency ----
        int base = (blockIdx.x - PREP_YB) * 1024 + threadIdx.x;
#pragma unroll
        for (int k = 0; k < 4; k++) {
            int e = base + k * 256;
            if (e < NE) {
                int th = (e / PERG) * TSTEP;
                int s = __ldg(&ei[e]);
                int d = __ldg(&ei[NE + e]);
                if (s >= th && d >= th) {
                    int slot = atomicAdd(&g_ideg[d], 1);
                    if (slot < MAXDEG) g_adj[d * MAXDEG + slot] = s;
                }
            }
        }
        return;
    }
    // ---- y path: per warp-tile of 16 nodes, y = W1a^T x ----
    extern __shared__ u64 sm[];
    u64* tables = sm;                          // 8 * 640 u64
    float* sWa = (float*)(sm + 8 * TBL_U64);   // 2048 f32

    for (int i = threadIdx.x; i < 2048; i += 256) sWa[i] = W1a[i];
    __syncthreads();

    int lane = threadIdx.x & 31;
    u64* xs = tables + (threadIdx.x >> 5) * TBL_U64;
    float* xsf = (float*)xs;
    int ln16 = lane & 15, c2 = lane >> 4;

    while (true) {
        int t = steal_tile(&g_ctr[0], lane);
        if (t >= NTILES) break;
        int nb = t * TILE_N;
        // stage 16 x-rows transposed
        const float4* src4 = (const float4*)x;
#pragma unroll
        for (int cc = 0; cc < 8; cc++) {
            int c = cc * 2 + c2;
            float4 v = src4[(nb + ln16) * 16 + c];
            float* p = xsf + (4 * c) * 20 + ln16;
            p[0] = v.x; p[20] = v.y; p[40] = v.z; p[60] = v.w;
        }
        __syncwarp();

        u64 acc[8];
#pragma unroll
        for (int i = 0; i < 8; i++) acc[i] = 0;
#pragma unroll 4
        for (int k = 0; k < 64; k++) {
            const ulonglong2* row = (const ulonglong2*)(xs + k * ROW_U64);
            float w = sWa[k * 32 + lane];
            u64 wd = pk2(w, w);
#pragma unroll
            for (int q = 0; q < 4; q++) {
                ulonglong2 x2 = row[q];
                acc[2 * q]     = ffma2(x2.x, wd, acc[2 * q]);
                acc[2 * q + 1] = ffma2(x2.y, wd, acc[2 * q + 1]);
            }
        }
#pragma unroll
        for (int p = 0; p < 8; p++) {
            float lo, hi;
            upk2(acc[p], lo, hi);
            int n0 = nb + 2 * p;
            g_y[n0 * 32 + lane] = lo;
            g_y[(n0 + 1) * 32 + lane] = hi;
        }
        __syncwarp();
    }
}

// ---------------- MLP1: gather y (32-dim) -> relu -> 32x64 -> relu -----------
__global__ __launch_bounds__(256, 4) void mlp1_kernel(
    const float* __restrict__ b1a,
    const float* __restrict__ W1b, const float* __restrict__ b1b) {
    extern __shared__ u64 sm[];
    u64* tables = sm;                          // 8 * 640 u64
    float* sWb = (float*)(sm + 8 * TBL_U64);   // 2048 f32

    for (int i = threadIdx.x; i < 2048; i += 256) sWb[i] = W1b[i];
    __syncthreads();

    int lane = threadIdx.x & 31;
    u64* xs = tables + (threadIdx.x >> 5) * TBL_U64;
    float* xsf = (float*)xs;

    float ba = b1a[lane];
    float bl = b1b[lane], bh = b1b[lane + 32];
    u64 bbL = pk2(bl, bl), bbH = pk2(bh, bh);

    u64 sA = 0, sB = 0, qA = 0, qB = 0;

    while (true) {
        int t = steal_tile(&g_ctr[1], lane);
        if (t >= NTILES) break;
        int nb = t * TILE_N;

        // ---- fused gather over y (32-dim rows): relu(y_d + sum y_src + b1a) ----
#pragma unroll 1
        for (int n = 0; n < TILE_N; n++) {
            int node = nb + n;
            int deg = min(__ldg(&g_ideg[node]), MAXDEG);
            const int* adj = g_adj + node * MAXDEG;
            float a0 = __ldg(&g_y[node * 32 + lane]);
            float t0 = 0.f, t1 = 0.f, t2 = 0.f, t3 = 0.f;
            int j = 0;
            for (; j + 4 <= deg; j += 4) {
                int4 s4 = __ldg((const int4*)(adj + j));
                t0 += __ldg(&g_y[s4.x * 32 + lane]);
                t1 += __ldg(&g_y[s4.y * 32 + lane]);
                t2 += __ldg(&g_y[s4.z * 32 + lane]);
                t3 += __ldg(&g_y[s4.w * 32 + lane]);
            }
            for (; j < deg; j++)
                t0 += __ldg(&g_y[__ldg(&adj[j]) * 32 + lane]);
            a0 += (t0 + t1) + (t2 + t3);
            xsf[lane * 20 + n] = fmaxf(a0 + ba, 0.f);
        }
        __syncwarp();

        // ---- layer b: K=32, 64 out ----
        u64 aO[8], aP[8];
#pragma unroll
        for (int i = 0; i < 8; i++) { aO[i] = bbL; aP[i] = bbH; }
#pragma unroll 4
        for (int k = 0; k < 32; k++) {
            const ulonglong2* row = (const ulonglong2*)(xs + k * ROW_U64);
            float wl = sWb[k * 64 + lane], wh = sWb[k * 64 + lane + 32];
            u64 wld = pk2(wl, wl), whd = pk2(wh, wh);
#pragma unroll
            for (int q = 0; q < 4; q++) {
                ulonglong2 x2 = row[q];
                aO[2 * q]     = ffma2(x2.x, wld, aO[2 * q]);
                aO[2 * q + 1] = ffma2(x2.y, wld, aO[2 * q + 1]);
                aP[2 * q]     = ffma2(x2.x, whd, aP[2 * q]);
                aP[2 * q + 1] = ffma2(x2.y, whd, aP[2 * q + 1]);
            }
        }

        // ---- epilogue: relu, store h1, stats ----
#pragma unroll
        for (int p = 0; p < 8; p++) {
            u64 O = relu2(aO[p]), P = relu2(aP[p]);
            float lo, hi, lo2, hi2;
            upk2(O, lo, hi); upk2(P, lo2, hi2);
            int n0 = nb + 2 * p;
            g_h1[n0 * 64 + lane] = lo;
            g_h1[(n0 + 1) * 64 + lane] = hi;
            g_h1[n0 * 64 + 32 + lane] = lo2;
            g_h1[(n0 + 1) * 64 + 32 + lane] = hi2;
            sA = add2(sA, O); qA = ffma2(O, O, qA);
            sB = add2(sB, P); qB = ffma2(P, P, qB);
        }
        __syncwarp();
    }

    float a, b;
    upk2(sA, a, b); atomicAdd(&g_stats1[lane], a + b);
    upk2(sB, a, b); atomicAdd(&g_stats1[lane + 32], a + b);
    upk2(qA, a, b); atomicAdd(&g_stats1[64 + lane], a + b);
    upk2(qB, a, b); atomicAdd(&g_stats1[96 + lane], a + b);
}

// ---------------- MLP2: fused gather + BN1 affine + 64->64->64 + pooling -----
__global__ __launch_bounds__(256, 3) void mlp2_kernel(
    const float* __restrict__ W2a, const float* __restrict__ b2a,
    const float* __restrict__ W2b, const float* __restrict__ b2b,
    const int* __restrict__ batch,
    const float* __restrict__ gamma1, const float* __restrict__ beta1) {
    extern __shared__ u64 sm[];
    u64* tables = sm;
    float* sWa = (float*)(sm + 8 * TBL_U64);   // 4096 f32
    float* sWb = sWa + 4096;                   // 4096 f32

    for (int i = threadIdx.x; i < 4096; i += 256) {
        sWa[i] = W2a[i];
        sWb[i] = W2b[i];
    }
    __syncthreads();

    int lane = threadIdx.x & 31;
    u64* xs = tables + (threadIdx.x >> 5) * TBL_U64;
    float* xsf = (float*)xs;

    // BN1 folded affine computed from stats (replaces finalize1 kernel)
    float aLo, aHi, bLo, bHi;
    {
        float m = g_stats1[lane] * (1.f / NN);
        float v = g_stats1[64 + lane] * (1.f / NN) - m * m;
        aLo = gamma1[lane] * rsqrtf(v + BN_EPS);
        bLo = beta1[lane] - m * aLo;
        float m2 = g_stats1[lane + 32] * (1.f / NN);
        float v2 = g_stats1[96 + lane] * (1.f / NN) - m2 * m2;
        aHi = gamma1[lane + 32] * rsqrtf(v2 + BN_EPS);
        bHi = beta1[lane + 32] - m2 * aHi;
    }

    float al = b2a[lane], ah = b2a[lane + 32];
    u64 baL = pk2(al, al), baH = pk2(ah, ah);
    float bl = b2b[lane], bh = b2b[lane + 32];
    u64 bbL = pk2(bl, bl), bbH = pk2(bh, bh);

    u64 sA = 0, sB = 0, qA = 0, qB = 0;
    u64 pA = 0, pB = 0;
    float crun = 0.f;
    int cg = -1;

    while (true) {
        int t = steal_tile(&g_ctr[2], lane);
        if (t >= NTILES) break;
        int nb = t * TILE_N;

        // ---- fused gather over h1 + BN1 affine, transposed store ----
        const float* feat = (const float*)g_h1;
#pragma unroll 1
        for (int n = 0; n < TILE_N; n++) {
            int node = nb + n;
            int deg = min(__ldg(&g_ideg[node]), MAXDEG);
            const int* adj = g_adj + node * MAXDEG;
            const float* self = feat + node * 64;
            float a0 = __ldg(&self[lane]);
            float a1 = __ldg(&self[lane + 32]);
            float t0 = 0.f, t1 = 0.f, t2 = 0.f, t3 = 0.f;
            int j = 0;
            for (; j + 2 <= deg; j += 2) {
                int s0 = __ldg(&adj[j]), s1 = __ldg(&adj[j + 1]);
                const float* r0 = feat + s0 * 64;
                const float* r1 = feat + s1 * 64;
                t0 += __ldg(&r0[lane]);
                t1 += __ldg(&r1[lane]);
                t2 += __ldg(&r0[lane + 32]);
                t3 += __ldg(&r1[lane + 32]);
            }
            if (j < deg) {
                const float* r0 = feat + __ldg(&adj[j]) * 64;
                t0 += __ldg(&r0[lane]);
                t2 += __ldg(&r0[lane + 32]);
            }
            a0 += t0 + t1;
            a1 += t2 + t3;
            float dg = 1.f + (float)deg;
            xsf[lane * 20 + n] = fmaf(dg, bLo, aLo * a0);
            xsf[(lane + 32) * 20 + n] = fmaf(dg, bHi, aHi * a1);
        }
        __syncwarp();

        // ---- layer a: K=64, 64 out ----
        u64 aO[8], aP[8];
#pragma unroll
        for (int i = 0; i < 8; i++) { aO[i] = baL; aP[i] = baH; }
#pragma unroll 4
        for (int k = 0; k < 64; k++) {
            const ulonglong2* row = (const ulonglong2*)(xs + k * ROW_U64);
            float wl = sWa[k * 64 + lane], wh = sWa[k * 64 + lane + 32];
            u64 wld = pk2(wl, wl), whd = pk2(wh, wh);
#pragma unroll
            for (int q = 0; q < 4; q++) {
                ulonglong2 x2 = row[q];
                aO[2 * q]     = ffma2(x2.x, wld, aO[2 * q]);
                aO[2 * q + 1] = ffma2(x2.y, wld, aO[2 * q + 1]);
                aP[2 * q]     = ffma2(x2.x, whd, aP[2 * q]);
                aP[2 * q + 1] = ffma2(x2.y, whd, aP[2 * q + 1]);
            }
        }
        __syncwarp();
        {
            u64* r0 = xs + lane * ROW_U64;
            u64* r1 = xs + (lane + 32) * ROW_U64;
#pragma unroll
            for (int q = 0; q < 8; q++) { r0[q] = relu2(aO[q]); r1[q] = relu2(aP[q]); }
        }
        __syncwarp();

        // ---- layer b: K=64, 64 out ----
#pragma unroll
        for (int i = 0; i < 8; i++) { aO[i] = bbL; aP[i] = bbH; }
#pragma unroll 4
        for (int k = 0; k < 64; k++) {
            const ulonglong2* row = (const ulonglong2*)(xs + k * ROW_U64);
            float wl = sWb[k * 64 + lane], wh = sWb[k * 64 + lane + 32];
            u64 wld = pk2(wl, wl), whd = pk2(wh, wh);
#pragma unroll
            for (int q = 0; q < 4; q++) {
                ulonglong2 x2 = row[q];
                aO[2 * q]     = ffma2(x2.x, wld, aO[2 * q]);
                aO[2 * q + 1] = ffma2(x2.y, wld, aO[2 * q + 1]);
                aP[2 * q]     = ffma2(x2.x, whd, aP[2 * q]);
                aP[2 * q + 1] = ffma2(x2.y, whd, aP[2 * q + 1]);
            }
        }

        // ---- epilogue: relu, stats, run-length pooling ----
#pragma unroll
        for (int p = 0; p < 8; p++) {
            u64 O = relu2(aO[p]), P = relu2(aP[p]);
            sA = add2(sA, O); qA = ffma2(O, O, qA);
            sB = add2(sB, P); qB = ffma2(P, P, qB);

            int2 bp = *((const int2*)(batch + nb + 2 * p));
            if (bp.x == cg && bp.y == cg) {
                pA = add2(pA, O); pB = add2(pB, P); crun += 2.f;
            } else {
                if (cg >= 0 && crun > 0.f) {
                    float a, b;
                    upk2(pA, a, b); atomicAdd(&g_gsum[cg * 64 + lane], a + b);
                    upk2(pB, a, b); atomicAdd(&g_gsum[cg * 64 + lane + 32], a + b);
                    if (lane == 0) atomicAdd(&g_cnt[cg], crun);
                }
                if (bp.x == bp.y) {
                    cg = bp.x; pA = O; pB = P; crun = 2.f;
                } else {
                    float a, b;
                    upk2(O, a, b);
                    atomicAdd(&g_gsum[bp.x * 64 + lane], a);
                    u64 tA = pk2(0.f, b);
                    upk2(P, a, b);
                    atomicAdd(&g_gsum[bp.x * 64 + lane + 32], a);
                    if (lane == 0) atomicAdd(&g_cnt[bp.x], 1.f);
                    cg = bp.y; pA = tA; pB = pk2(0.f, b); crun = 1.f;
                }
            }
        }
        __syncwarp();
    }
    if (cg >= 0 && crun > 0.f) {
        float a, b;
        upk2(pA, a, b); atomicAdd(&g_gsum[cg * 64 + lane], a + b);
        upk2(pB, a, b); atomicAdd(&g_gsum[cg * 64 + lane + 32], a + b);
        if (lane == 0) atomicAdd(&g_cnt[cg], crun);
    }
    float a, b;
    upk2(sA, a, b); atomicAdd(&g_stats2[lane], a + b);
    upk2(sB, a, b); atomicAdd(&g_stats2[lane + 32], a + b);
    upk2(qA, a, b); atomicAdd(&g_stats2[64 + lane], a + b);
    upk2(qB, a, b); atomicAdd(&g_stats2[96 + lane], a + b);
}

__global__ void finalize2_kernel(const float* __restrict__ gamma,
                                 const float* __restrict__ beta,
                                 float* __restrict__ out) {
    int f = threadIdx.x;
    int g = blockIdx.x;
    float mean = g_stats2[f] * (1.f / NN);
    float var = g_stats2[64 + f] * (1.f / NN) - mean * mean;
    float inv = rsqrtf(var + BN_EPS);
    float cnt = fmaxf(g_cnt[g], 1.f);
    float m = g_gsum[g * 64 + f] / cnt;
    out[g * 64 + f] = (m - mean) * inv * gamma[f] + beta[f];
}

// ---------------- launch -----------------------------------------------------
extern "C" void kernel_launch(void* const* d_in, const int* in_sizes, int n_in,
                              void* d_out, int out_size) {
    const float* x = (const float*)d_in[0];
    const int* ei = (const int*)d_in[1];
    const int* batch = (const int*)d_in[2];

    int base = 3;
    while (base < n_in && in_sizes[base] == 1) base++;
    const float* W1a = (const float*)d_in[base + 0];
    const float* b1a = (const float*)d_in[base + 1];
    const float* W1b = (const float*)d_in[base + 2];
    const float* b1b = (const float*)d_in[base + 3];
    const float* g1  = (const float*)d_in[base + 4];
    const float* be1 = (const float*)d_in[base + 5];
    const float* W2a = (const float*)d_in[base + 6];
    const float* b2a = (const float*)d_in[base + 7];
    const float* W2b = (const float*)d_in[base + 8];
    const float* b2b = (const float*)d_in[base + 9];
    const float* g2  = (const float*)d_in[base + 10];
    const float* be2 = (const float*)d_in[base + 11];
    float* out = (float*)d_out;

    const int smemP = 8 * TBL_U64 * 8 + 2048 * 4;       // 49152
    const int smem1 = 8 * TBL_U64 * 8 + 2048 * 4;       // 49152
    const int smem2 = 8 * TBL_U64 * 8 + 2 * 4096 * 4;   // 73728
    cudaFuncSetAttribute(prep_kernel, cudaFuncAttributeMaxDynamicSharedMemorySize, smemP);
    cudaFuncSetAttribute(mlp1_kernel, cudaFuncAttributeMaxDynamicSharedMemorySize, smem1);
    cudaFuncSetAttribute(mlp2_kernel, cudaFuncAttributeMaxDynamicSharedMemorySize, smem2);

    zero_kernel<<<(NN + 255) / 256, 256>>>();
    prep_kernel<<<PREP_YB + PREP_AB, 256, smemP>>>(x, ei, W1a);
    mlp1_kernel<<<592, 256, smem1>>>(b1a, W1b, b1b);
    mlp2_kernel<<<444, 256, smem2>>>(W2a, b2a, W2b, b2b, batch, g1, be1);
    finalize2_kernel<<<NG, 64>>>(g2, be2, out);
}